// round 6
// baseline (speedup 1.0000x reference)
#include <cuda_runtime.h>
#include <cstdint>

// Problem constants
#define Bn 64
#define Tn 512
#define Dn 1024
#define Cn 32
#define BT (Bn*Tn)          // 32768

// Scratch (small, no device allocation allowed)
__device__ float g_logZ[Bn];
__device__ float g_score[Bn];
__device__ int   g_msum[Bn];

// ---------------------------------------------------------------------------
// packed f32x2 helpers (Blackwell sm_100+)
// ---------------------------------------------------------------------------
__device__ __forceinline__ unsigned long long pack2(float lo, float hi) {
    unsigned long long r;
    asm("mov.b64 %0, {%1, %2};" : "=l"(r) : "f"(lo), "f"(hi));
    return r;
}
__device__ __forceinline__ void fma2(unsigned long long& d, unsigned long long a, unsigned long long b) {
    asm("fma.rn.f32x2 %0, %1, %2, %0;" : "+l"(d) : "l"(a), "l"(b));
}
__device__ __forceinline__ void unpack2(unsigned long long v, float& lo, float& hi) {
    asm("mov.b64 {%0, %1}, %2;" : "=f"(lo), "=f"(hi) : "l"(v));
}

// ---------------------------------------------------------------------------
// Kernel 1: logits[r][c] = sum_d V[r][d] * W[c][d] + b[c]
//   r in [0, 32768), c in [0, 32), d in [0, 1024)
//   One thread per row; W staged through smem in 4 chunks of 256 K.
// ---------------------------------------------------------------------------
__device__ __forceinline__ void do_k(float vs, const float* swk, unsigned long long* acc) {
    unsigned long long vv = pack2(vs, vs);
    const ulonglong2* sw = reinterpret_cast<const ulonglong2*>(swk);
#pragma unroll
    for (int q = 0; q < 8; q++) {
        ulonglong2 w = sw[q];
        fma2(acc[2*q],   vv, w.x);
        fma2(acc[2*q+1], vv, w.y);
    }
}

__global__ __launch_bounds__(256) void gemm_kernel(
    const float* __restrict__ V,   // [BT, D]
    const float* __restrict__ W,   // [C, D]
    const float* __restrict__ bias,// [C]
    float* __restrict__ out)       // [BT, C]  (== d_out + 1, 4B aligned only)
{
    __shared__ __align__(16) float sW[256 * 32];   // 32 KB: Wt[k_local][c]

    const int tid = threadIdx.x;
    const int row = blockIdx.x * 256 + tid;

    unsigned long long acc[16];
#pragma unroll
    for (int p = 0; p < 16; p++) acc[p] = pack2(bias[2*p], bias[2*p+1]);

    const float4* vp = reinterpret_cast<const float4*>(V + (size_t)row * Dn);

    for (int kc = 0; kc < 4; kc++) {
        __syncthreads();
        // stage Wt chunk: sW[kl*32 + c] = W[c*1024 + kc*256 + kl]
#pragma unroll 4
        for (int i = tid; i < 8192; i += 256) {
            int c  = i & 31;
            int kl = i >> 5;
            sW[i] = W[c * Dn + kc * 256 + kl];
        }
        __syncthreads();

        float4 v = vp[kc * 64];
#pragma unroll 2
        for (int k4 = 0; k4 < 64; k4++) {
            float4 vn = v;
            if (k4 < 63) vn = vp[kc * 64 + k4 + 1];
            const float* swb = sW + (k4 * 4) * 32;
            do_k(v.x, swb,      acc);
            do_k(v.y, swb + 32, acc);
            do_k(v.z, swb + 64, acc);
            do_k(v.w, swb + 96, acc);
            v = vn;
        }
    }

    // Scalar stores (out base is only 4B-aligned).
    float* orow = out + (size_t)row * Cn;
#pragma unroll
    for (int p = 0; p < 16; p++) {
        float f0, f1;
        unpack2(acc[p], f0, f1);
        orow[2*p]     = f0;
        orow[2*p + 1] = f1;
    }
}

// ---------------------------------------------------------------------------
// Kernel 2: 192 one-warp blocks.
//   blocks [0,64):    forward log-sum-exp recursion -> g_logZ[b]
//   blocks [64,128):  Viterbi recursion + backtrace -> tags, path_scores
//   blocks [128,192): gold score -> g_score[b], g_msum[b]
// ---------------------------------------------------------------------------
__global__ __launch_bounds__(32) void crf_kernel(
    const float* __restrict__ logits,  // [B, T, C]
    const int*   __restrict__ mask,    // [B, T]
    const int*   __restrict__ targets, // [B, T]
    const float* __restrict__ trans,   // [C, C]
    const float* __restrict__ startt,  // [C]
    const float* __restrict__ endt,    // [C]
    float* __restrict__ tags_out,      // [B, T] as float
    float* __restrict__ path_out)      // [B]
{
    __shared__ unsigned char bp[(Tn - 1) * Cn];  // 16352 B backpointers
    __shared__ unsigned char tg[Tn];

    const unsigned FULL = 0xffffffffu;
    const int j = threadIdx.x;
    const int bid = blockIdx.x;

    if (bid < 64) {
        // ---------------- forward (log-sum-exp) ----------------
        const int b = bid;
        float E[32];
#pragma unroll
        for (int i = 0; i < 32; i++) E[i] = __expf(trans[i * Cn + j]);

        const float* lg = logits + (size_t)b * Tn * Cn + j;
        const int*   mk = mask + b * Tn;

        float alpha = startt[j] + lg[0];
        float lt1 = lg[1 * Cn];  int m1 = mk[1];
        float lt2 = lg[2 * Cn];  int m2 = mk[2];

        for (int t = 1; t < Tn; t++) {
            float lt = lt1; int mt = m1;
            lt1 = lt2; m1 = m2;
            if (t + 2 < Tn) { lt2 = lg[(t + 2) * Cn]; m2 = mk[t + 2]; }

            float a0 = __shfl_sync(FULL, alpha, 0);
            float p  = __expf(alpha - a0);
            float s0 = 0.f, s1 = 0.f, s2 = 0.f, s3 = 0.f;
#pragma unroll
            for (int i = 0; i < 32; i += 4) {
                s0 = fmaf(__shfl_sync(FULL, p, i),     E[i],     s0);
                s1 = fmaf(__shfl_sync(FULL, p, i + 1), E[i + 1], s1);
                s2 = fmaf(__shfl_sync(FULL, p, i + 2), E[i + 2], s2);
                s3 = fmaf(__shfl_sync(FULL, p, i + 3), E[i + 3], s3);
            }
            float s = (s0 + s1) + (s2 + s3);
            float anew = a0 + __logf(s) + lt;
            alpha = (mt > 0) ? anew : alpha;
        }

        // logZ = LSE(alpha + end)
        float v = alpha + endt[j];
        float m = v;
#pragma unroll
        for (int o = 16; o; o >>= 1) m = fmaxf(m, __shfl_xor_sync(FULL, m, o));
        float e = __expf(v - m);
#pragma unroll
        for (int o = 16; o; o >>= 1) e += __shfl_xor_sync(FULL, e, o);
        if (j == 0) g_logZ[b] = m + __logf(e);

    } else if (bid < 128) {
        // ---------------- Viterbi ----------------
        const int b = bid - 64;
        float Tr[32];
#pragma unroll
        for (int i = 0; i < 32; i++) Tr[i] = trans[i * Cn + j];

        const float* lg = logits + (size_t)b * Tn * Cn + j;
        const int*   mk = mask + b * Tn;

        float delta = startt[j] + lg[0];
        float lt1 = lg[1 * Cn];  int m1 = mk[1];
        float lt2 = lg[2 * Cn];  int m2 = mk[2];

        for (int t = 1; t < Tn; t++) {
            float lt = lt1; int mt = m1;
            lt1 = lt2; m1 = m2;
            if (t + 2 < Tn) { lt2 = lg[(t + 2) * Cn]; m2 = mk[t + 2]; }

            float cand[32];
#pragma unroll
            for (int i = 0; i < 32; i++)
                cand[i] = __shfl_sync(FULL, delta, i) + Tr[i];

            // exact max tree (FMNMX is exact; order irrelevant for max)
            float tr0[16];
#pragma unroll
            for (int i = 0; i < 16; i++) tr0[i] = fmaxf(cand[2*i], cand[2*i+1]);
#pragma unroll
            for (int i = 0; i < 8; i++)  tr0[i] = fmaxf(tr0[2*i], tr0[2*i+1]);
#pragma unroll
            for (int i = 0; i < 4; i++)  tr0[i] = fmaxf(tr0[2*i], tr0[2*i+1]);
            tr0[0] = fmaxf(tr0[0], tr0[1]);
            tr0[1] = fmaxf(tr0[2], tr0[3]);
            float mval = fmaxf(tr0[0], tr0[1]);

            // first-argmax: lowest i with cand[i] == max
            unsigned e0 = 0, e1 = 0, e2 = 0, e3 = 0;
#pragma unroll
            for (int i = 0; i < 32; i += 4) {
                e0 |= (cand[i]     == mval) ? (1u << i)       : 0u;
                e1 |= (cand[i + 1] == mval) ? (1u << (i + 1)) : 0u;
                e2 |= (cand[i + 2] == mval) ? (1u << (i + 2)) : 0u;
                e3 |= (cand[i + 3] == mval) ? (1u << (i + 3)) : 0u;
            }
            int bpv = __ffs((e0 | e1) | (e2 | e3)) - 1;

            float dn = mval + lt;
            if (mt > 0) { delta = dn; } else { bpv = j; }
            bp[(t - 1) * Cn + j] = (unsigned char)bpv;
        }

        // final scores / last tag
        float fin = delta + endt[j];
        float pm = fin;
#pragma unroll
        for (int o = 16; o; o >>= 1) pm = fmaxf(pm, __shfl_xor_sync(FULL, pm, o));
        unsigned bal = __ballot_sync(FULL, fin == pm);
        int last_tag = __ffs(bal) - 1;
        if (j == 0) path_out[b] = pm;

        __syncwarp();
        if (j == 0) {
            int tag = last_tag;
            tg[Tn - 1] = (unsigned char)tag;
            for (int t = Tn - 2; t >= 0; t--) {
                tag = bp[t * Cn + tag];
                tg[t] = (unsigned char)tag;
            }
        }
        __syncwarp();
#pragma unroll
        for (int idx = j; idx < Tn; idx += 32)
            tags_out[(size_t)b * Tn + idx] = (float)tg[idx];

    } else {
        // ---------------- gold score ----------------
        const int b = bid - 128;
        const int*   tgt = targets + b * Tn;
        const int*   mk  = mask + b * Tn;
        const float* lg  = logits + (size_t)b * Tn * Cn;

        float s = 0.f;
        int msum = 0;
        for (int t = j; t < Tn; t += 32) {
            int g  = tgt[t];
            int mi = mk[t];
            float mf = (float)mi;
            msum += mi;
            if (t >= 1)      s += trans[tgt[t - 1] * Cn + g] * mf;
            if (t <= Tn - 2) s += lg[t * Cn + g] * mf;
        }
#pragma unroll
        for (int o = 16; o; o >>= 1) {
            s    += __shfl_xor_sync(FULL, s, o);
            msum += __shfl_xor_sync(FULL, msum, o);
        }
        if (j == 0) {
            int li = msum - 1;
            int ltag = tgt[li];
            s += startt[tgt[0]];
            s += endt[ltag];
            s += lg[(Tn - 1) * Cn + ltag] * (float)mk[Tn - 1];
            g_score[b] = s;
            g_msum[b]  = msum;
        }
    }
}

// ---------------------------------------------------------------------------
// Kernel 3: loss = -sum_b(score_b - logZ_b) / sum(mask)
// ---------------------------------------------------------------------------
__global__ __launch_bounds__(64) void finalize_kernel(float* __restrict__ d_out)
{
    const unsigned FULL = 0xffffffffu;
    int tid = threadIdx.x;
    float d = g_score[tid] - g_logZ[tid];
    int   ms = g_msum[tid];
#pragma unroll
    for (int o = 16; o; o >>= 1) {
        d  += __shfl_xor_sync(FULL, d, o);
        ms += __shfl_xor_sync(FULL, ms, o);
    }
    __shared__ float sd[2];
    __shared__ int   sm[2];
    if ((tid & 31) == 0) { sd[tid >> 5] = d; sm[tid >> 5] = ms; }
    __syncthreads();
    if (tid == 0) {
        float total  = sd[0] + sd[1];
        int   mtotal = sm[0] + sm[1];
        d_out[0] = -total / (float)mtotal;
    }
}

// ---------------------------------------------------------------------------
// Launch
//   d_in: 0 vectors f32[B,T,D], 1 mask i32[B,T], 2 targets i32[B,T],
//         3 W f32[C,D], 4 b f32[C], 5 transitions f32[C,C],
//         6 start_transitions f32[C], 7 end_transitions f32[C]
//   d_out (f32): [loss(1), logits(B*T*C), tags(B*T), path_scores(B)]
// ---------------------------------------------------------------------------
extern "C" void kernel_launch(void* const* d_in, const int* in_sizes, int n_in,
                              void* d_out, int out_size)
{
    const float* V      = (const float*)d_in[0];
    const int*   mask   = (const int*)  d_in[1];
    const int*   tgt    = (const int*)  d_in[2];
    const float* W      = (const float*)d_in[3];
    const float* bias   = (const float*)d_in[4];
    const float* trans  = (const float*)d_in[5];
    const float* startt = (const float*)d_in[6];
    const float* endt   = (const float*)d_in[7];

    float* out    = (float*)d_out;
    float* logits = out + 1;
    float* tags   = out + 1 + (size_t)BT * Cn;
    float* path   = tags + BT;

    gemm_kernel<<<BT / 256, 256>>>(V, W, bias, logits);
    crf_kernel<<<192, 32>>>(logits, mask, tgt, trans, startt, endt, tags, path);
    finalize_kernel<<<1, 64>>>(out);
}

// round 7
// speedup vs baseline: 1.0002x; 1.0002x over previous
#include <cuda_runtime.h>
#include <cstdint>

// Problem constants
#define Bn 64
#define Tn 512
#define Dn 1024
#define Cn 32
#define BT (Bn*Tn)          // 32768

// Scratch (small, no device allocation allowed)
__device__ float g_logZ[Bn];
__device__ float g_score[Bn];
__device__ int   g_msum[Bn];

// ---------------------------------------------------------------------------
// packed f32x2 helpers (Blackwell sm_100+)
// ---------------------------------------------------------------------------
__device__ __forceinline__ unsigned long long pack2(float lo, float hi) {
    unsigned long long r;
    asm("mov.b64 %0, {%1, %2};" : "=l"(r) : "f"(lo), "f"(hi));
    return r;
}
__device__ __forceinline__ void fma2(unsigned long long& d, unsigned long long a, unsigned long long b) {
    asm("fma.rn.f32x2 %0, %1, %2, %0;" : "+l"(d) : "l"(a), "l"(b));
}
__device__ __forceinline__ void unpack2(unsigned long long v, float& lo, float& hi) {
    asm("mov.b64 {%0, %1}, %2;" : "=f"(lo), "=f"(hi) : "l"(v));
}

// ---------------------------------------------------------------------------
// Kernel 1: logits[r][c] = sum_d V[r][d] * W[c][d] + b[c]
//   r in [0, 32768), c in [0, 32), d in [0, 1024)
//   One thread per row; W staged through smem in 4 chunks of 256 K.
// ---------------------------------------------------------------------------
__device__ __forceinline__ void do_k(float vs, const float* swk, unsigned long long* acc) {
    unsigned long long vv = pack2(vs, vs);
    const ulonglong2* sw = reinterpret_cast<const ulonglong2*>(swk);
#pragma unroll
    for (int q = 0; q < 8; q++) {
        ulonglong2 w = sw[q];
        fma2(acc[2*q],   vv, w.x);
        fma2(acc[2*q+1], vv, w.y);
    }
}

__global__ __launch_bounds__(256) void gemm_kernel(
    const float* __restrict__ V,   // [BT, D]
    const float* __restrict__ W,   // [C, D]
    const float* __restrict__ bias,// [C]
    float* __restrict__ out)       // [BT, C]  (== d_out + 1, 4B aligned only)
{
    __shared__ __align__(16) float sW[256 * 32];   // 32 KB: Wt[k_local][c]

    const int tid = threadIdx.x;
    const int row = blockIdx.x * 256 + tid;

    unsigned long long acc[16];
#pragma unroll
    for (int p = 0; p < 16; p++) acc[p] = pack2(bias[2*p], bias[2*p+1]);

    const float4* vp = reinterpret_cast<const float4*>(V + (size_t)row * Dn);

    for (int kc = 0; kc < 4; kc++) {
        __syncthreads();
        // stage Wt chunk: sW[kl*32 + c] = W[c*1024 + kc*256 + kl]
#pragma unroll 4
        for (int i = tid; i < 8192; i += 256) {
            int c  = i & 31;
            int kl = i >> 5;
            sW[i] = W[c * Dn + kc * 256 + kl];
        }
        __syncthreads();

        float4 v = vp[kc * 64];
#pragma unroll 2
        for (int k4 = 0; k4 < 64; k4++) {
            float4 vn = v;
            if (k4 < 63) vn = vp[kc * 64 + k4 + 1];
            const float* swb = sW + (k4 * 4) * 32;
            do_k(v.x, swb,      acc);
            do_k(v.y, swb + 32, acc);
            do_k(v.z, swb + 64, acc);
            do_k(v.w, swb + 96, acc);
            v = vn;
        }
    }

    // Scalar stores (out base is only 4B-aligned).
    float* orow = out + (size_t)row * Cn;
#pragma unroll
    for (int p = 0; p < 16; p++) {
        float f0, f1;
        unpack2(acc[p], f0, f1);
        orow[2*p]     = f0;
        orow[2*p + 1] = f1;
    }
}

// ---------------------------------------------------------------------------
// Kernel 2: 192 one-warp blocks.
//   blocks [0,64):    forward log-sum-exp recursion -> g_logZ[b]
//   blocks [64,128):  Viterbi recursion + backtrace -> tags, path_scores
//   blocks [128,192): gold score -> g_score[b], g_msum[b]
// ---------------------------------------------------------------------------
__global__ __launch_bounds__(32) void crf_kernel(
    const float* __restrict__ logits,  // [B, T, C]
    const int*   __restrict__ mask,    // [B, T]
    const int*   __restrict__ targets, // [B, T]
    const float* __restrict__ trans,   // [C, C]
    const float* __restrict__ startt,  // [C]
    const float* __restrict__ endt,    // [C]
    float* __restrict__ tags_out,      // [B, T] as float
    float* __restrict__ path_out)      // [B]
{
    __shared__ unsigned char bp[(Tn - 1) * Cn];  // 16352 B backpointers
    __shared__ unsigned char tg[Tn];

    const unsigned FULL = 0xffffffffu;
    const int j = threadIdx.x;
    const int bid = blockIdx.x;

    if (bid < 64) {
        // ---------------- forward (log-sum-exp) ----------------
        const int b = bid;
        float E[32];
#pragma unroll
        for (int i = 0; i < 32; i++) E[i] = __expf(trans[i * Cn + j]);

        const float* lg = logits + (size_t)b * Tn * Cn + j;
        const int*   mk = mask + b * Tn;

        float alpha = startt[j] + lg[0];
        float lt1 = lg[1 * Cn];  int m1 = mk[1];
        float lt2 = lg[2 * Cn];  int m2 = mk[2];

        for (int t = 1; t < Tn; t++) {
            float lt = lt1; int mt = m1;
            lt1 = lt2; m1 = m2;
            if (t + 2 < Tn) { lt2 = lg[(t + 2) * Cn]; m2 = mk[t + 2]; }

            float a0 = __shfl_sync(FULL, alpha, 0);
            float p  = __expf(alpha - a0);
            float s0 = 0.f, s1 = 0.f, s2 = 0.f, s3 = 0.f;
#pragma unroll
            for (int i = 0; i < 32; i += 4) {
                s0 = fmaf(__shfl_sync(FULL, p, i),     E[i],     s0);
                s1 = fmaf(__shfl_sync(FULL, p, i + 1), E[i + 1], s1);
                s2 = fmaf(__shfl_sync(FULL, p, i + 2), E[i + 2], s2);
                s3 = fmaf(__shfl_sync(FULL, p, i + 3), E[i + 3], s3);
            }
            float s = (s0 + s1) + (s2 + s3);
            float anew = a0 + __logf(s) + lt;
            alpha = (mt > 0) ? anew : alpha;
        }

        // logZ = LSE(alpha + end)
        float v = alpha + endt[j];
        float m = v;
#pragma unroll
        for (int o = 16; o; o >>= 1) m = fmaxf(m, __shfl_xor_sync(FULL, m, o));
        float e = __expf(v - m);
#pragma unroll
        for (int o = 16; o; o >>= 1) e += __shfl_xor_sync(FULL, e, o);
        if (j == 0) g_logZ[b] = m + __logf(e);

    } else if (bid < 128) {
        // ---------------- Viterbi ----------------
        const int b = bid - 64;
        float Tr[32];
#pragma unroll
        for (int i = 0; i < 32; i++) Tr[i] = trans[i * Cn + j];

        const float* lg = logits + (size_t)b * Tn * Cn + j;
        const int*   mk = mask + b * Tn;

        float delta = startt[j] + lg[0];
        float lt1 = lg[1 * Cn];  int m1 = mk[1];
        float lt2 = lg[2 * Cn];  int m2 = mk[2];

        for (int t = 1; t < Tn; t++) {
            float lt = lt1; int mt = m1;
            lt1 = lt2; m1 = m2;
            if (t + 2 < Tn) { lt2 = lg[(t + 2) * Cn]; m2 = mk[t + 2]; }

            float cand[32];
#pragma unroll
            for (int i = 0; i < 32; i++)
                cand[i] = __shfl_sync(FULL, delta, i) + Tr[i];

            // exact max tree (FMNMX is exact; order irrelevant for max)
            float tr0[16];
#pragma unroll
            for (int i = 0; i < 16; i++) tr0[i] = fmaxf(cand[2*i], cand[2*i+1]);
#pragma unroll
            for (int i = 0; i < 8; i++)  tr0[i] = fmaxf(tr0[2*i], tr0[2*i+1]);
#pragma unroll
            for (int i = 0; i < 4; i++)  tr0[i] = fmaxf(tr0[2*i], tr0[2*i+1]);
            tr0[0] = fmaxf(tr0[0], tr0[1]);
            tr0[1] = fmaxf(tr0[2], tr0[3]);
            float mval = fmaxf(tr0[0], tr0[1]);

            // first-argmax: lowest i with cand[i] == max
            unsigned e0 = 0, e1 = 0, e2 = 0, e3 = 0;
#pragma unroll
            for (int i = 0; i < 32; i += 4) {
                e0 |= (cand[i]     == mval) ? (1u << i)       : 0u;
                e1 |= (cand[i + 1] == mval) ? (1u << (i + 1)) : 0u;
                e2 |= (cand[i + 2] == mval) ? (1u << (i + 2)) : 0u;
                e3 |= (cand[i + 3] == mval) ? (1u << (i + 3)) : 0u;
            }
            int bpv = __ffs((e0 | e1) | (e2 | e3)) - 1;

            float dn = mval + lt;
            if (mt > 0) { delta = dn; } else { bpv = j; }
            bp[(t - 1) * Cn + j] = (unsigned char)bpv;
        }

        // final scores / last tag
        float fin = delta + endt[j];
        float pm = fin;
#pragma unroll
        for (int o = 16; o; o >>= 1) pm = fmaxf(pm, __shfl_xor_sync(FULL, pm, o));
        unsigned bal = __ballot_sync(FULL, fin == pm);
        int last_tag = __ffs(bal) - 1;
        if (j == 0) path_out[b] = pm;

        __syncwarp();
        if (j == 0) {
            int tag = last_tag;
            tg[Tn - 1] = (unsigned char)tag;
            for (int t = Tn - 2; t >= 0; t--) {
                tag = bp[t * Cn + tag];
                tg[t] = (unsigned char)tag;
            }
        }
        __syncwarp();
#pragma unroll
        for (int idx = j; idx < Tn; idx += 32)
            tags_out[(size_t)b * Tn + idx] = (float)tg[idx];

    } else {
        // ---------------- gold score ----------------
        const int b = bid - 128;
        const int*   tgt = targets + b * Tn;
        const int*   mk  = mask + b * Tn;
        const float* lg  = logits + (size_t)b * Tn * Cn;

        float s = 0.f;
        int msum = 0;
        for (int t = j; t < Tn; t += 32) {
            int g  = tgt[t];
            int mi = mk[t];
            float mf = (float)mi;
            msum += mi;
            if (t >= 1)      s += trans[tgt[t - 1] * Cn + g] * mf;
            if (t <= Tn - 2) s += lg[t * Cn + g] * mf;
        }
#pragma unroll
        for (int o = 16; o; o >>= 1) {
            s    += __shfl_xor_sync(FULL, s, o);
            msum += __shfl_xor_sync(FULL, msum, o);
        }
        if (j == 0) {
            int li = msum - 1;
            int ltag = tgt[li];
            s += startt[tgt[0]];
            s += endt[ltag];
            s += lg[(Tn - 1) * Cn + ltag] * (float)mk[Tn - 1];
            g_score[b] = s;
            g_msum[b]  = msum;
        }
    }
}

// ---------------------------------------------------------------------------
// Kernel 3: loss = -sum_b(score_b - logZ_b) / sum(mask)
// ---------------------------------------------------------------------------
__global__ __launch_bounds__(64) void finalize_kernel(float* __restrict__ d_out)
{
    const unsigned FULL = 0xffffffffu;
    int tid = threadIdx.x;
    float d = g_score[tid] - g_logZ[tid];
    int   ms = g_msum[tid];
#pragma unroll
    for (int o = 16; o; o >>= 1) {
        d  += __shfl_xor_sync(FULL, d, o);
        ms += __shfl_xor_sync(FULL, ms, o);
    }
    __shared__ float sd[2];
    __shared__ int   sm[2];
    if ((tid & 31) == 0) { sd[tid >> 5] = d; sm[tid >> 5] = ms; }
    __syncthreads();
    if (tid == 0) {
        float total  = sd[0] + sd[1];
        int   mtotal = sm[0] + sm[1];
        d_out[0] = -total / (float)mtotal;
    }
}

// ---------------------------------------------------------------------------
// Launch
//   d_in: 0 vectors f32[B,T,D], 1 mask i32[B,T], 2 targets i32[B,T],
//         3 W f32[C,D], 4 b f32[C], 5 transitions f32[C,C],
//         6 start_transitions f32[C], 7 end_transitions f32[C]
//   d_out (f32): [loss(1), logits(B*T*C), tags(B*T), path_scores(B)]
// ---------------------------------------------------------------------------
extern "C" void kernel_launch(void* const* d_in, const int* in_sizes, int n_in,
                              void* d_out, int out_size)
{
    const float* V      = (const float*)d_in[0];
    const int*   mask   = (const int*)  d_in[1];
    const int*   tgt    = (const int*)  d_in[2];
    const float* W      = (const float*)d_in[3];
    const float* bias   = (const float*)d_in[4];
    const float* trans  = (const float*)d_in[5];
    const float* startt = (const float*)d_in[6];
    const float* endt   = (const float*)d_in[7];

    float* out    = (float*)d_out;
    float* logits = out + 1;
    float* tags   = out + 1 + (size_t)BT * Cn;
    float* path   = tags + BT;

    gemm_kernel<<<BT / 256, 256>>>(V, W, bias, logits);
    crf_kernel<<<192, 32>>>(logits, mask, tgt, trans, startt, endt, tags, path);
    finalize_kernel<<<1, 64>>>(out);
}

// round 8
// speedup vs baseline: 1.0008x; 1.0006x over previous
#include <cuda_runtime.h>
#include <cstdint>

// Problem constants
#define Bn 64
#define Tn 512
#define Dn 1024
#define Cn 32
#define BT (Bn*Tn)          // 32768

// Scratch (small, no device allocation allowed)
__device__ float g_logZ[Bn];
__device__ float g_score[Bn];
__device__ int   g_msum[Bn];

// ---------------------------------------------------------------------------
// packed f32x2 helpers (Blackwell sm_100+)
// ---------------------------------------------------------------------------
__device__ __forceinline__ unsigned long long pack2(float lo, float hi) {
    unsigned long long r;
    asm("mov.b64 %0, {%1, %2};" : "=l"(r) : "f"(lo), "f"(hi));
    return r;
}
__device__ __forceinline__ void fma2(unsigned long long& d, unsigned long long a, unsigned long long b) {
    asm("fma.rn.f32x2 %0, %1, %2, %0;" : "+l"(d) : "l"(a), "l"(b));
}
__device__ __forceinline__ void unpack2(unsigned long long v, float& lo, float& hi) {
    asm("mov.b64 {%0, %1}, %2;" : "=f"(lo), "=f"(hi) : "l"(v));
}

// ---------------------------------------------------------------------------
// Kernel 1: logits[r][c] = sum_d V[r][d] * W[c][d] + b[c]
//   r in [0, 32768), c in [0, 32), d in [0, 1024)
//   One thread per row; W staged through smem in 4 chunks of 256 K.
// ---------------------------------------------------------------------------
__device__ __forceinline__ void do_k(float vs, const float* swk, unsigned long long* acc) {
    unsigned long long vv = pack2(vs, vs);
    const ulonglong2* sw = reinterpret_cast<const ulonglong2*>(swk);
#pragma unroll
    for (int q = 0; q < 8; q++) {
        ulonglong2 w = sw[q];
        fma2(acc[2*q],   vv, w.x);
        fma2(acc[2*q+1], vv, w.y);
    }
}

__global__ __launch_bounds__(256) void gemm_kernel(
    const float* __restrict__ V,   // [BT, D]
    const float* __restrict__ W,   // [C, D]
    const float* __restrict__ bias,// [C]
    float* __restrict__ out)       // [BT, C]  (== d_out + 1, 4B aligned only)
{
    __shared__ __align__(16) float sW[256 * 32];   // 32 KB: Wt[k_local][c]

    const int tid = threadIdx.x;
    const int row = blockIdx.x * 256 + tid;

    unsigned long long acc[16];
#pragma unroll
    for (int p = 0; p < 16; p++) acc[p] = pack2(bias[2*p], bias[2*p+1]);

    const float4* vp = reinterpret_cast<const float4*>(V + (size_t)row * Dn);

    for (int kc = 0; kc < 4; kc++) {
        __syncthreads();
        // stage Wt chunk: sW[kl*32 + c] = W[c*1024 + kc*256 + kl]
#pragma unroll 4
        for (int i = tid; i < 8192; i += 256) {
            int c  = i & 31;
            int kl = i >> 5;
            sW[i] = W[c * Dn + kc * 256 + kl];
        }
        __syncthreads();

        float4 v = vp[kc * 64];
#pragma unroll 2
        for (int k4 = 0; k4 < 64; k4++) {
            float4 vn = v;
            if (k4 < 63) vn = vp[kc * 64 + k4 + 1];
            const float* swb = sW + (k4 * 4) * 32;
            do_k(v.x, swb,      acc);
            do_k(v.y, swb + 32, acc);
            do_k(v.z, swb + 64, acc);
            do_k(v.w, swb + 96, acc);
            v = vn;
        }
    }

    // Scalar stores (out base is only 4B-aligned).
    float* orow = out + (size_t)row * Cn;
#pragma unroll
    for (int p = 0; p < 16; p++) {
        float f0, f1;
        unpack2(acc[p], f0, f1);
        orow[2*p]     = f0;
        orow[2*p + 1] = f1;
    }
}

// ---------------------------------------------------------------------------
// Kernel 2: 192 one-warp blocks.
//   blocks [0,64):    forward log-sum-exp recursion -> g_logZ[b]
//   blocks [64,128):  Viterbi recursion + backtrace -> tags, path_scores
//   blocks [128,192): gold score -> g_score[b], g_msum[b]
// ---------------------------------------------------------------------------
__global__ __launch_bounds__(32) void crf_kernel(
    const float* __restrict__ logits,  // [B, T, C]
    const int*   __restrict__ mask,    // [B, T]
    const int*   __restrict__ targets, // [B, T]
    const float* __restrict__ trans,   // [C, C]
    const float* __restrict__ startt,  // [C]
    const float* __restrict__ endt,    // [C]
    float* __restrict__ tags_out,      // [B, T] as float
    float* __restrict__ path_out)      // [B]
{
    __shared__ unsigned char bp[(Tn - 1) * Cn];  // 16352 B backpointers
    __shared__ unsigned char tg[Tn];

    const unsigned FULL = 0xffffffffu;
    const int j = threadIdx.x;
    const int bid = blockIdx.x;

    if (bid < 64) {
        // ---------------- forward (log-sum-exp) ----------------
        const int b = bid;
        float E[32];
#pragma unroll
        for (int i = 0; i < 32; i++) E[i] = __expf(trans[i * Cn + j]);

        const float* lg = logits + (size_t)b * Tn * Cn + j;
        const int*   mk = mask + b * Tn;

        float alpha = startt[j] + lg[0];
        float lt1 = lg[1 * Cn];  int m1 = mk[1];
        float lt2 = lg[2 * Cn];  int m2 = mk[2];

        for (int t = 1; t < Tn; t++) {
            float lt = lt1; int mt = m1;
            lt1 = lt2; m1 = m2;
            if (t + 2 < Tn) { lt2 = lg[(t + 2) * Cn]; m2 = mk[t + 2]; }

            float a0 = __shfl_sync(FULL, alpha, 0);
            float p  = __expf(alpha - a0);
            float s0 = 0.f, s1 = 0.f, s2 = 0.f, s3 = 0.f;
#pragma unroll
            for (int i = 0; i < 32; i += 4) {
                s0 = fmaf(__shfl_sync(FULL, p, i),     E[i],     s0);
                s1 = fmaf(__shfl_sync(FULL, p, i + 1), E[i + 1], s1);
                s2 = fmaf(__shfl_sync(FULL, p, i + 2), E[i + 2], s2);
                s3 = fmaf(__shfl_sync(FULL, p, i + 3), E[i + 3], s3);
            }
            float s = (s0 + s1) + (s2 + s3);
            float anew = a0 + __logf(s) + lt;
            alpha = (mt > 0) ? anew : alpha;
        }

        // logZ = LSE(alpha + end)
        float v = alpha + endt[j];
        float m = v;
#pragma unroll
        for (int o = 16; o; o >>= 1) m = fmaxf(m, __shfl_xor_sync(FULL, m, o));
        float e = __expf(v - m);
#pragma unroll
        for (int o = 16; o; o >>= 1) e += __shfl_xor_sync(FULL, e, o);
        if (j == 0) g_logZ[b] = m + __logf(e);

    } else if (bid < 128) {
        // ---------------- Viterbi ----------------
        const int b = bid - 64;
        float Tr[32];
#pragma unroll
        for (int i = 0; i < 32; i++) Tr[i] = trans[i * Cn + j];

        const float* lg = logits + (size_t)b * Tn * Cn + j;
        const int*   mk = mask + b * Tn;

        float delta = startt[j] + lg[0];
        float lt1 = lg[1 * Cn];  int m1 = mk[1];
        float lt2 = lg[2 * Cn];  int m2 = mk[2];

        for (int t = 1; t < Tn; t++) {
            float lt = lt1; int mt = m1;
            lt1 = lt2; m1 = m2;
            if (t + 2 < Tn) { lt2 = lg[(t + 2) * Cn]; m2 = mk[t + 2]; }

            float cand[32];
#pragma unroll
            for (int i = 0; i < 32; i++)
                cand[i] = __shfl_sync(FULL, delta, i) + Tr[i];

            // exact max tree (FMNMX is exact; order irrelevant for max)
            float tr0[16];
#pragma unroll
            for (int i = 0; i < 16; i++) tr0[i] = fmaxf(cand[2*i], cand[2*i+1]);
#pragma unroll
            for (int i = 0; i < 8; i++)  tr0[i] = fmaxf(tr0[2*i], tr0[2*i+1]);
#pragma unroll
            for (int i = 0; i < 4; i++)  tr0[i] = fmaxf(tr0[2*i], tr0[2*i+1]);
            tr0[0] = fmaxf(tr0[0], tr0[1]);
            tr0[1] = fmaxf(tr0[2], tr0[3]);
            float mval = fmaxf(tr0[0], tr0[1]);

            // first-argmax: lowest i with cand[i] == max
            unsigned e0 = 0, e1 = 0, e2 = 0, e3 = 0;
#pragma unroll
            for (int i = 0; i < 32; i += 4) {
                e0 |= (cand[i]     == mval) ? (1u << i)       : 0u;
                e1 |= (cand[i + 1] == mval) ? (1u << (i + 1)) : 0u;
                e2 |= (cand[i + 2] == mval) ? (1u << (i + 2)) : 0u;
                e3 |= (cand[i + 3] == mval) ? (1u << (i + 3)) : 0u;
            }
            int bpv = __ffs((e0 | e1) | (e2 | e3)) - 1;

            float dn = mval + lt;
            if (mt > 0) { delta = dn; } else { bpv = j; }
            bp[(t - 1) * Cn + j] = (unsigned char)bpv;
        }

        // final scores / last tag
        float fin = delta + endt[j];
        float pm = fin;
#pragma unroll
        for (int o = 16; o; o >>= 1) pm = fmaxf(pm, __shfl_xor_sync(FULL, pm, o));
        unsigned bal = __ballot_sync(FULL, fin == pm);
        int last_tag = __ffs(bal) - 1;
        if (j == 0) path_out[b] = pm;

        __syncwarp();
        if (j == 0) {
            int tag = last_tag;
            tg[Tn - 1] = (unsigned char)tag;
            for (int t = Tn - 2; t >= 0; t--) {
                tag = bp[t * Cn + tag];
                tg[t] = (unsigned char)tag;
            }
        }
        __syncwarp();
#pragma unroll
        for (int idx = j; idx < Tn; idx += 32)
            tags_out[(size_t)b * Tn + idx] = (float)tg[idx];

    } else {
        // ---------------- gold score ----------------
        const int b = bid - 128;
        const int*   tgt = targets + b * Tn;
        const int*   mk  = mask + b * Tn;
        const float* lg  = logits + (size_t)b * Tn * Cn;

        float s = 0.f;
        int msum = 0;
        for (int t = j; t < Tn; t += 32) {
            int g  = tgt[t];
            int mi = mk[t];
            float mf = (float)mi;
            msum += mi;
            if (t >= 1)      s += trans[tgt[t - 1] * Cn + g] * mf;
            if (t <= Tn - 2) s += lg[t * Cn + g] * mf;
        }
#pragma unroll
        for (int o = 16; o; o >>= 1) {
            s    += __shfl_xor_sync(FULL, s, o);
            msum += __shfl_xor_sync(FULL, msum, o);
        }
        if (j == 0) {
            int li = msum - 1;
            int ltag = tgt[li];
            s += startt[tgt[0]];
            s += endt[ltag];
            s += lg[(Tn - 1) * Cn + ltag] * (float)mk[Tn - 1];
            g_score[b] = s;
            g_msum[b]  = msum;
        }
    }
}

// ---------------------------------------------------------------------------
// Kernel 3: loss = -sum_b(score_b - logZ_b) / sum(mask)
// ---------------------------------------------------------------------------
__global__ __launch_bounds__(64) void finalize_kernel(float* __restrict__ d_out)
{
    const unsigned FULL = 0xffffffffu;
    int tid = threadIdx.x;
    float d = g_score[tid] - g_logZ[tid];
    int   ms = g_msum[tid];
#pragma unroll
    for (int o = 16; o; o >>= 1) {
        d  += __shfl_xor_sync(FULL, d, o);
        ms += __shfl_xor_sync(FULL, ms, o);
    }
    __shared__ float sd[2];
    __shared__ int   sm[2];
    if ((tid & 31) == 0) { sd[tid >> 5] = d; sm[tid >> 5] = ms; }
    __syncthreads();
    if (tid == 0) {
        float total  = sd[0] + sd[1];
        int   mtotal = sm[0] + sm[1];
        d_out[0] = -total / (float)mtotal;
    }
}

// ---------------------------------------------------------------------------
// Launch
//   d_in: 0 vectors f32[B,T,D], 1 mask i32[B,T], 2 targets i32[B,T],
//         3 W f32[C,D], 4 b f32[C], 5 transitions f32[C,C],
//         6 start_transitions f32[C], 7 end_transitions f32[C]
//   d_out (f32): [loss(1), logits(B*T*C), tags(B*T), path_scores(B)]
// ---------------------------------------------------------------------------
extern "C" void kernel_launch(void* const* d_in, const int* in_sizes, int n_in,
                              void* d_out, int out_size)
{
    const float* V      = (const float*)d_in[0];
    const int*   mask   = (const int*)  d_in[1];
    const int*   tgt    = (const int*)  d_in[2];
    const float* W      = (const float*)d_in[3];
    const float* bias   = (const float*)d_in[4];
    const float* trans  = (const float*)d_in[5];
    const float* startt = (const float*)d_in[6];
    const float* endt   = (const float*)d_in[7];

    float* out    = (float*)d_out;
    float* logits = out + 1;
    float* tags   = out + 1 + (size_t)BT * Cn;
    float* path   = tags + BT;

    gemm_kernel<<<BT / 256, 256>>>(V, W, bias, logits);
    crf_kernel<<<192, 32>>>(logits, mask, tgt, trans, startt, endt, tags, path);
    finalize_kernel<<<1, 64>>>(out);
}

// round 9
// speedup vs baseline: 1.0072x; 1.0064x over previous
#include <cuda_runtime.h>
#include <cstdint>

// Problem constants
#define Bn 64
#define Tn 512
#define Dn 1024
#define Cn 32
#define BT (Bn*Tn)          // 32768

// Scratch (small, no device allocation allowed)
__device__ float g_logZ[Bn];
__device__ float g_score[Bn];
__device__ int   g_msum[Bn];

// ---------------------------------------------------------------------------
// packed f32x2 helpers (Blackwell sm_100+)
// ---------------------------------------------------------------------------
__device__ __forceinline__ unsigned long long pack2(float lo, float hi) {
    unsigned long long r;
    asm("mov.b64 %0, {%1, %2};" : "=l"(r) : "f"(lo), "f"(hi));
    return r;
}
__device__ __forceinline__ void fma2(unsigned long long& d, unsigned long long a, unsigned long long b) {
    asm("fma.rn.f32x2 %0, %1, %2, %0;" : "+l"(d) : "l"(a), "l"(b));
}
__device__ __forceinline__ void unpack2(unsigned long long v, float& lo, float& hi) {
    asm("mov.b64 {%0, %1}, %2;" : "=f"(lo), "=f"(hi) : "l"(v));
}

// ---------------------------------------------------------------------------
// Kernel 1: logits[r][c] = sum_d V[r][d] * W[c][d] + b[c]
//   r in [0, 32768), c in [0, 32), d in [0, 1024)
//   One thread per row; W staged through smem in 4 chunks of 256 K.
// ---------------------------------------------------------------------------
__device__ __forceinline__ void do_k(float vs, const float* swk, unsigned long long* acc) {
    unsigned long long vv = pack2(vs, vs);
    const ulonglong2* sw = reinterpret_cast<const ulonglong2*>(swk);
#pragma unroll
    for (int q = 0; q < 8; q++) {
        ulonglong2 w = sw[q];
        fma2(acc[2*q],   vv, w.x);
        fma2(acc[2*q+1], vv, w.y);
    }
}

__global__ __launch_bounds__(256) void gemm_kernel(
    const float* __restrict__ V,   // [BT, D]
    const float* __restrict__ W,   // [C, D]
    const float* __restrict__ bias,// [C]
    float* __restrict__ out)       // [BT, C]  (== d_out + 1, 4B aligned only)
{
    __shared__ __align__(16) float sW[256 * 32];   // 32 KB: Wt[k_local][c]

    const int tid = threadIdx.x;
    const int row = blockIdx.x * 256 + tid;

    unsigned long long acc[16];
#pragma unroll
    for (int p = 0; p < 16; p++) acc[p] = pack2(bias[2*p], bias[2*p+1]);

    const float4* vp = reinterpret_cast<const float4*>(V + (size_t)row * Dn);

    for (int kc = 0; kc < 4; kc++) {
        __syncthreads();
        // stage Wt chunk: sW[kl*32 + c] = W[c*1024 + kc*256 + kl]
#pragma unroll 4
        for (int i = tid; i < 8192; i += 256) {
            int c  = i & 31;
            int kl = i >> 5;
            sW[i] = W[c * Dn + kc * 256 + kl];
        }
        __syncthreads();

        float4 v = vp[kc * 64];
#pragma unroll 2
        for (int k4 = 0; k4 < 64; k4++) {
            float4 vn = v;
            if (k4 < 63) vn = vp[kc * 64 + k4 + 1];
            const float* swb = sW + (k4 * 4) * 32;
            do_k(v.x, swb,      acc);
            do_k(v.y, swb + 32, acc);
            do_k(v.z, swb + 64, acc);
            do_k(v.w, swb + 96, acc);
            v = vn;
        }
    }

    // Scalar stores (out base is only 4B-aligned).
    float* orow = out + (size_t)row * Cn;
#pragma unroll
    for (int p = 0; p < 16; p++) {
        float f0, f1;
        unpack2(acc[p], f0, f1);
        orow[2*p]     = f0;
        orow[2*p + 1] = f1;
    }
}

// ---------------------------------------------------------------------------
// Kernel 2: 192 one-warp blocks.
//   blocks [0,64):    forward log-sum-exp recursion -> g_logZ[b]
//   blocks [64,128):  Viterbi recursion + backtrace -> tags, path_scores
//   blocks [128,192): gold score -> g_score[b], g_msum[b]
// ---------------------------------------------------------------------------
__global__ __launch_bounds__(32) void crf_kernel(
    const float* __restrict__ logits,  // [B, T, C]
    const int*   __restrict__ mask,    // [B, T]
    const int*   __restrict__ targets, // [B, T]
    const float* __restrict__ trans,   // [C, C]
    const float* __restrict__ startt,  // [C]
    const float* __restrict__ endt,    // [C]
    float* __restrict__ tags_out,      // [B, T] as float
    float* __restrict__ path_out)      // [B]
{
    __shared__ unsigned char bp[(Tn - 1) * Cn];  // 16352 B backpointers
    __shared__ unsigned char tg[Tn];

    const unsigned FULL = 0xffffffffu;
    const int j = threadIdx.x;
    const int bid = blockIdx.x;

    if (bid < 64) {
        // ---------------- forward (log-sum-exp) ----------------
        const int b = bid;
        float E[32];
#pragma unroll
        for (int i = 0; i < 32; i++) E[i] = __expf(trans[i * Cn + j]);

        const float* lg = logits + (size_t)b * Tn * Cn + j;
        const int*   mk = mask + b * Tn;

        float alpha = startt[j] + lg[0];
        float lt1 = lg[1 * Cn];  int m1 = mk[1];
        float lt2 = lg[2 * Cn];  int m2 = mk[2];

        for (int t = 1; t < Tn; t++) {
            float lt = lt1; int mt = m1;
            lt1 = lt2; m1 = m2;
            if (t + 2 < Tn) { lt2 = lg[(t + 2) * Cn]; m2 = mk[t + 2]; }

            float a0 = __shfl_sync(FULL, alpha, 0);
            float p  = __expf(alpha - a0);
            float s0 = 0.f, s1 = 0.f, s2 = 0.f, s3 = 0.f;
#pragma unroll
            for (int i = 0; i < 32; i += 4) {
                s0 = fmaf(__shfl_sync(FULL, p, i),     E[i],     s0);
                s1 = fmaf(__shfl_sync(FULL, p, i + 1), E[i + 1], s1);
                s2 = fmaf(__shfl_sync(FULL, p, i + 2), E[i + 2], s2);
                s3 = fmaf(__shfl_sync(FULL, p, i + 3), E[i + 3], s3);
            }
            float s = (s0 + s1) + (s2 + s3);
            float anew = a0 + __logf(s) + lt;
            alpha = (mt > 0) ? anew : alpha;
        }

        // logZ = LSE(alpha + end)
        float v = alpha + endt[j];
        float m = v;
#pragma unroll
        for (int o = 16; o; o >>= 1) m = fmaxf(m, __shfl_xor_sync(FULL, m, o));
        float e = __expf(v - m);
#pragma unroll
        for (int o = 16; o; o >>= 1) e += __shfl_xor_sync(FULL, e, o);
        if (j == 0) g_logZ[b] = m + __logf(e);

    } else if (bid < 128) {
        // ---------------- Viterbi ----------------
        const int b = bid - 64;
        float Tr[32];
#pragma unroll
        for (int i = 0; i < 32; i++) Tr[i] = trans[i * Cn + j];

        const float* lg = logits + (size_t)b * Tn * Cn + j;
        const int*   mk = mask + b * Tn;

        float delta = startt[j] + lg[0];
        float lt1 = lg[1 * Cn];  int m1 = mk[1];
        float lt2 = lg[2 * Cn];  int m2 = mk[2];

        for (int t = 1; t < Tn; t++) {
            float lt = lt1; int mt = m1;
            lt1 = lt2; m1 = m2;
            if (t + 2 < Tn) { lt2 = lg[(t + 2) * Cn]; m2 = mk[t + 2]; }

            float cand[32];
#pragma unroll
            for (int i = 0; i < 32; i++)
                cand[i] = __shfl_sync(FULL, delta, i) + Tr[i];

            // exact max tree (FMNMX is exact; order irrelevant for max)
            float tr0[16];
#pragma unroll
            for (int i = 0; i < 16; i++) tr0[i] = fmaxf(cand[2*i], cand[2*i+1]);
#pragma unroll
            for (int i = 0; i < 8; i++)  tr0[i] = fmaxf(tr0[2*i], tr0[2*i+1]);
#pragma unroll
            for (int i = 0; i < 4; i++)  tr0[i] = fmaxf(tr0[2*i], tr0[2*i+1]);
            tr0[0] = fmaxf(tr0[0], tr0[1]);
            tr0[1] = fmaxf(tr0[2], tr0[3]);
            float mval = fmaxf(tr0[0], tr0[1]);

            // first-argmax: lowest i with cand[i] == max
            unsigned e0 = 0, e1 = 0, e2 = 0, e3 = 0;
#pragma unroll
            for (int i = 0; i < 32; i += 4) {
                e0 |= (cand[i]     == mval) ? (1u << i)       : 0u;
                e1 |= (cand[i + 1] == mval) ? (1u << (i + 1)) : 0u;
                e2 |= (cand[i + 2] == mval) ? (1u << (i + 2)) : 0u;
                e3 |= (cand[i + 3] == mval) ? (1u << (i + 3)) : 0u;
            }
            int bpv = __ffs((e0 | e1) | (e2 | e3)) - 1;

            float dn = mval + lt;
            if (mt > 0) { delta = dn; } else { bpv = j; }
            bp[(t - 1) * Cn + j] = (unsigned char)bpv;
        }

        // final scores / last tag
        float fin = delta + endt[j];
        float pm = fin;
#pragma unroll
        for (int o = 16; o; o >>= 1) pm = fmaxf(pm, __shfl_xor_sync(FULL, pm, o));
        unsigned bal = __ballot_sync(FULL, fin == pm);
        int last_tag = __ffs(bal) - 1;
        if (j == 0) path_out[b] = pm;

        __syncwarp();
        if (j == 0) {
            int tag = last_tag;
            tg[Tn - 1] = (unsigned char)tag;
            for (int t = Tn - 2; t >= 0; t--) {
                tag = bp[t * Cn + tag];
                tg[t] = (unsigned char)tag;
            }
        }
        __syncwarp();
#pragma unroll
        for (int idx = j; idx < Tn; idx += 32)
            tags_out[(size_t)b * Tn + idx] = (float)tg[idx];

    } else {
        // ---------------- gold score ----------------
        const int b = bid - 128;
        const int*   tgt = targets + b * Tn;
        const int*   mk  = mask + b * Tn;
        const float* lg  = logits + (size_t)b * Tn * Cn;

        float s = 0.f;
        int msum = 0;
        for (int t = j; t < Tn; t += 32) {
            int g  = tgt[t];
            int mi = mk[t];
            float mf = (float)mi;
            msum += mi;
            if (t >= 1)      s += trans[tgt[t - 1] * Cn + g] * mf;
            if (t <= Tn - 2) s += lg[t * Cn + g] * mf;
        }
#pragma unroll
        for (int o = 16; o; o >>= 1) {
            s    += __shfl_xor_sync(FULL, s, o);
            msum += __shfl_xor_sync(FULL, msum, o);
        }
        if (j == 0) {
            int li = msum - 1;
            int ltag = tgt[li];
            s += startt[tgt[0]];
            s += endt[ltag];
            s += lg[(Tn - 1) * Cn + ltag] * (float)mk[Tn - 1];
            g_score[b] = s;
            g_msum[b]  = msum;
        }
    }
}

// ---------------------------------------------------------------------------
// Kernel 3: loss = -sum_b(score_b - logZ_b) / sum(mask)
// ---------------------------------------------------------------------------
__global__ __launch_bounds__(64) void finalize_kernel(float* __restrict__ d_out)
{
    const unsigned FULL = 0xffffffffu;
    int tid = threadIdx.x;
    float d = g_score[tid] - g_logZ[tid];
    int   ms = g_msum[tid];
#pragma unroll
    for (int o = 16; o; o >>= 1) {
        d  += __shfl_xor_sync(FULL, d, o);
        ms += __shfl_xor_sync(FULL, ms, o);
    }
    __shared__ float sd[2];
    __shared__ int   sm[2];
    if ((tid & 31) == 0) { sd[tid >> 5] = d; sm[tid >> 5] = ms; }
    __syncthreads();
    if (tid == 0) {
        float total  = sd[0] + sd[1];
        int   mtotal = sm[0] + sm[1];
        d_out[0] = -total / (float)mtotal;
    }
}

// ---------------------------------------------------------------------------
// Launch
//   d_in: 0 vectors f32[B,T,D], 1 mask i32[B,T], 2 targets i32[B,T],
//         3 W f32[C,D], 4 b f32[C], 5 transitions f32[C,C],
//         6 start_transitions f32[C], 7 end_transitions f32[C]
//   d_out (f32): [loss(1), logits(B*T*C), tags(B*T), path_scores(B)]
// ---------------------------------------------------------------------------
extern "C" void kernel_launch(void* const* d_in, const int* in_sizes, int n_in,
                              void* d_out, int out_size)
{
    const float* V      = (const float*)d_in[0];
    const int*   mask   = (const int*)  d_in[1];
    const int*   tgt    = (const int*)  d_in[2];
    const float* W      = (const float*)d_in[3];
    const float* bias   = (const float*)d_in[4];
    const float* trans  = (const float*)d_in[5];
    const float* startt = (const float*)d_in[6];
    const float* endt   = (const float*)d_in[7];

    float* out    = (float*)d_out;
    float* logits = out + 1;
    float* tags   = out + 1 + (size_t)BT * Cn;
    float* path   = tags + BT;

    gemm_kernel<<<BT / 256, 256>>>(V, W, bias, logits);
    crf_kernel<<<192, 32>>>(logits, mask, tgt, trans, startt, endt, tags, path);
    finalize_kernel<<<1, 64>>>(out);
}